// round 4
// baseline (speedup 1.0000x reference)
#include <cuda_runtime.h>
#include <cuda_bf16.h>
#include <cstdint>

#define D      128      // D_IN = D_OUT
#define NMAX   100000
#define EMAX   1600000

// Scratch (device globals; no allocation allowed)
__device__ __nv_bfloat16 g_xh[NMAX * D];   // x hi (bf16)
__device__ __nv_bfloat16 g_xl[NMAX * D];   // x lo (residual bf16)
__device__ float         g_y [NMAX * D];   // y = x @ W2
__device__ int           g_count [NMAX];   // edges per dst
__device__ int           g_off   [NMAX];   // CSR row offsets
__device__ int           g_cursor[NMAX];   // fill cursors
__device__ uint2         g_edges [EMAX];   // dst-sorted (src, val_bits)

// ============================================================================
// PTX helpers (base ISA: cp.async / ldmatrix / mma.sync)
// ============================================================================
__device__ __forceinline__ uint32_t smem_to_u32(const void* p) {
    uint32_t a;
    asm("{ .reg .u64 t; cvta.to.shared.u64 t, %1; cvt.u32.u64 %0, t; }"
        : "=r"(a) : "l"(p));
    return a;
}
#define CP_ASYNC16(dst, src, sz) \
    asm volatile("cp.async.cg.shared.global [%0], [%1], 16, %2;" \
        :: "r"(dst), "l"(src), "r"(sz))
#define CP_COMMIT() asm volatile("cp.async.commit_group;" ::: "memory")
#define CP_WAIT1()  asm volatile("cp.async.wait_group 1;"  ::: "memory")

#define LDSM_X4(r0,r1,r2,r3,addr) \
    asm volatile("ldmatrix.sync.aligned.m8n8.x4.shared.b16 {%0,%1,%2,%3}, [%4];" \
        : "=r"(r0), "=r"(r1), "=r"(r2), "=r"(r3) : "r"(addr))
#define LDSM_X4T(r0,r1,r2,r3,addr) \
    asm volatile("ldmatrix.sync.aligned.m8n8.x4.trans.shared.b16 {%0,%1,%2,%3}, [%4];" \
        : "=r"(r0), "=r"(r1), "=r"(r2), "=r"(r3) : "r"(addr))

#define MMA16816(c, a, b) \
    asm volatile("mma.sync.aligned.m16n8k16.row.col.f32.bf16.bf16.f32 " \
        "{%0,%1,%2,%3}, {%4,%5,%6,%7}, {%8,%9}, {%0,%1,%2,%3};" \
        : "+f"((c)[0]), "+f"((c)[1]), "+f"((c)[2]), "+f"((c)[3]) \
        : "r"((a)[0]), "r"((a)[1]), "r"((a)[2]), "r"((a)[3]), \
          "r"((b)[0]), "r"((b)[1]))

// ============================================================================
// Kernel 1: split x into bf16 hi/lo + zero the dst histogram
// ============================================================================
__global__ void convert_kernel(const float* __restrict__ x, int n4, int nnodes) {
    int i = blockIdx.x * blockDim.x + threadIdx.x;
    if (i < nnodes) g_count[i] = 0;
    if (i >= n4) return;
    float4 v = reinterpret_cast<const float4*>(x)[i];
    __nv_bfloat162 h0 = __floats2bfloat162_rn(v.x, v.y);
    __nv_bfloat162 h1 = __floats2bfloat162_rn(v.z, v.w);
    float r0 = v.x - __bfloat162float(h0.x);
    float r1 = v.y - __bfloat162float(h0.y);
    float r2 = v.z - __bfloat162float(h1.x);
    float r3 = v.w - __bfloat162float(h1.y);
    __nv_bfloat162 l0 = __floats2bfloat162_rn(r0, r1);
    __nv_bfloat162 l1 = __floats2bfloat162_rn(r2, r3);
    reinterpret_cast<uint2*>(g_xh)[i] = make_uint2(*(uint32_t*)&h0, *(uint32_t*)&h1);
    reinterpret_cast<uint2*>(g_xl)[i] = make_uint2(*(uint32_t*)&l0, *(uint32_t*)&l1);
}

// ============================================================================
// Kernel 2: histogram edges by dst
// ============================================================================
__global__ void hist_kernel(const int* __restrict__ edst, int E) {
    int i = blockIdx.x * blockDim.x + threadIdx.x;
    if (i < E) atomicAdd(&g_count[edst[i]], 1);
}

// ============================================================================
// Kernel 3: exclusive scan of g_count -> g_off (+ init cursors). 1 block.
// ============================================================================
__global__ __launch_bounds__(1024, 1)
void scan_kernel(int n) {
    __shared__ int ssum[1024];
    const int t = threadIdx.x;
    const int chunk = (n + 1023) >> 10;
    const int lo = t * chunk;
    const int hi = min(lo + chunk, n);

    int s = 0;
    for (int i = lo; i < hi; i++) s += g_count[i];
    ssum[t] = s;
    __syncthreads();

    // inclusive Hillis-Steele scan over 1024 partials
    for (int off = 1; off < 1024; off <<= 1) {
        int u = (t >= off) ? ssum[t - off] : 0;
        __syncthreads();
        if (t >= off) ssum[t] += u;
        __syncthreads();
    }
    int run = ssum[t] - s;   // exclusive prefix for this chunk
    for (int i = lo; i < hi; i++) {
        g_off[i]    = run;
        g_cursor[i] = run;
        run += g_count[i];
    }
}

// ============================================================================
// Kernel 4: permute edges into dst-sorted order
// ============================================================================
__global__ void fill_kernel(const int*   __restrict__ esrc,
                            const int*   __restrict__ edst,
                            const float* __restrict__ eval_,
                            int E) {
    int i = blockIdx.x * blockDim.x + threadIdx.x;
    if (i >= E) return;
    int d   = edst[i];
    int pos = atomicAdd(&g_cursor[d], 1);
    g_edges[pos] = make_uint2((uint32_t)esrc[i], __float_as_uint(eval_[i]));
}

// ============================================================================
// Kernel 5: persistent split-bf16 GEMM via mma.sync
//   (m_tile, nh): nh=0 -> d_out = x@W1 + b ; nh=1 -> g_y = x@W2
// ============================================================================
#define GT 256
#define AS_OFF(buf,hl) ((uint32_t)(((buf)<<1 | (hl)) * 32768))
#define BS_OFF(hl)     ((uint32_t)(131072 + (hl) * 32768))
#define SM_TOTAL       196608

__device__ __forceinline__ void load_A_tile(uint32_t smem_base, int buf,
                                            int node0, int N, int tid) {
#pragma unroll
    for (int i = 0; i < 8; i++) {
        int idx  = tid + (i << 8);
        int row  = idx >> 4;
        int cc   = idx & 15;
        int node = node0 + row;
        uint32_t sz    = (node < N) ? 16u : 0u;
        uint32_t chunk = (uint32_t)(cc ^ (row & 7));
        uint32_t doff  = (uint32_t)row * 256u + chunk * 16u;
        const __nv_bfloat16* sh = g_xh + (size_t)node * D + cc * 8;
        const __nv_bfloat16* sl = g_xl + (size_t)node * D + cc * 8;
        CP_ASYNC16(smem_base + AS_OFF(buf, 0) + doff, sh, sz);
        CP_ASYNC16(smem_base + AS_OFF(buf, 1) + doff, sl, sz);
    }
}

__global__ __launch_bounds__(GT, 1)
void gemm_kernel(const float* __restrict__ W,
                 const float* __restrict__ bias,
                 float* __restrict__ out,
                 int N) {
    extern __shared__ char smem[];
    uint32_t smem_base = smem_to_u32(smem);
    const int tid  = threadIdx.x;
    const int lane = tid & 31;
    const int wid  = tid >> 5;
    const int warp_m = (wid & 3) << 5;
    const int warp_n = (wid >> 2) << 6;

    const int num_tiles = (N + 127) >> 7;
    const int total = num_tiles * 2;
    int cur_nh = -1;

    int item = blockIdx.x;
    int buf = 0;
    if (item < total) load_A_tile(smem_base, 0, (item % num_tiles) << 7, N, tid);
    CP_COMMIT();

    for (; item < total; item += gridDim.x) {
        const int m_tile = item % num_tiles;
        const int nh     = item / num_tiles;
        const int node0  = m_tile << 7;

        int next = item + gridDim.x;
        if (next < total)
            load_A_tile(smem_base, buf ^ 1, (next % num_tiles) << 7, N, tid);
        CP_COMMIT();

        if (nh != cur_nh) {
            cur_nh = nh;
#pragma unroll
            for (int j = 0; j < 32; j++) {
                int idx = tid + (j << 8);
                int k   = idx >> 6;
                int n   = (idx & 63) << 1;
                const float* wp = W + ((size_t)(nh * 128 + k)) * 128 + n;
                float w0 = wp[0], w1 = wp[1];
                __nv_bfloat162 h = __floats2bfloat162_rn(w0, w1);
                float q0 = w0 - __bfloat162float(h.x);
                float q1 = w1 - __bfloat162float(h.y);
                __nv_bfloat162 l = __floats2bfloat162_rn(q0, q1);
                uint32_t boff = (uint32_t)k * 256u
                              + (uint32_t)(((n >> 3) ^ (k & 7)) << 4)
                              + (uint32_t)((n & 7) << 1);
                *reinterpret_cast<uint32_t*>(smem + BS_OFF(0) + boff) = *(uint32_t*)&h;
                *reinterpret_cast<uint32_t*>(smem + BS_OFF(1) + boff) = *(uint32_t*)&l;
            }
        }

        CP_WAIT1();
        __syncthreads();

        float acc[2][8][4];
#pragma unroll
        for (int mi = 0; mi < 2; mi++)
#pragma unroll
            for (int ni = 0; ni < 8; ni++)
#pragma unroll
                for (int q = 0; q < 4; q++) acc[mi][ni][q] = 0.f;

#pragma unroll
        for (int ks = 0; ks < 8; ks++) {
            uint32_t ah[2][4], al[2][4];
#pragma unroll
            for (int mi = 0; mi < 2; mi++) {
                int row = warp_m + (mi << 4) + (lane & 15);
                int cb  = (ks << 1) + (lane >> 4);
                uint32_t addr = smem_base + AS_OFF(buf, 0)
                              + (uint32_t)row * 256u
                              + (uint32_t)((cb ^ (row & 7)) << 4);
                LDSM_X4(ah[mi][0], ah[mi][1], ah[mi][2], ah[mi][3], addr);
                LDSM_X4(al[mi][0], al[mi][1], al[mi][2], al[mi][3], addr + 32768u);
            }
            uint32_t bh[8][2], bl[8][2];
#pragma unroll
            for (int nj = 0; nj < 4; nj++) {
                int row = (ks << 4) + (lane & 15);
                int cb  = (warp_n >> 3) + (nj << 1) + (lane >> 4);
                uint32_t addr = smem_base + BS_OFF(0)
                              + (uint32_t)row * 256u
                              + (uint32_t)((cb ^ (row & 7)) << 4);
                LDSM_X4T(bh[2*nj][0], bh[2*nj][1], bh[2*nj+1][0], bh[2*nj+1][1], addr);
                LDSM_X4T(bl[2*nj][0], bl[2*nj][1], bl[2*nj+1][0], bl[2*nj+1][1],
                         addr + 32768u);
            }
#pragma unroll
            for (int mi = 0; mi < 2; mi++)
#pragma unroll
                for (int ni = 0; ni < 8; ni++) {
                    MMA16816(acc[mi][ni], ah[mi], bh[ni]);
                    MMA16816(acc[mi][ni], ah[mi], bl[ni]);
                    MMA16816(acc[mi][ni], al[mi], bh[ni]);
                }
        }

        float* dst = (nh == 0) ? out : g_y;
#pragma unroll
        for (int ni = 0; ni < 8; ni++) {
            int col = warp_n + (ni << 3) + ((lane & 3) << 1);
            float b0 = 0.f, b1 = 0.f;
            if (nh == 0) { b0 = bias[col]; b1 = bias[col + 1]; }
#pragma unroll
            for (int mi = 0; mi < 2; mi++) {
                int r = warp_m + (mi << 4) + (lane >> 2);
                int node = node0 + r;
                if (node < N) {
                    float2 v = make_float2(acc[mi][ni][0] + b0, acc[mi][ni][1] + b1);
                    *reinterpret_cast<float2*>(dst + (size_t)node * D + col) = v;
                }
                int node2 = node + 8;
                if (node2 < N) {
                    float2 v = make_float2(acc[mi][ni][2] + b0, acc[mi][ni][3] + b1);
                    *reinterpret_cast<float2*>(dst + (size_t)node2 * D + col) = v;
                }
            }
        }
        __syncthreads();
        buf ^= 1;
    }
}

// ============================================================================
// Kernel 6: CSR aggregate.  Warp per dst row:
//   out[d] += sum_{e in seg(d)} val_e * y[src_e]   (register accumulation)
// ============================================================================
__global__ void aggregate_kernel(float* __restrict__ out, int N) {
    int warp = (blockIdx.x * blockDim.x + threadIdx.x) >> 5;
    int lane = threadIdx.x & 31;
    if (warp >= N) return;

    int cnt = g_count[warp];
    if (cnt == 0) return;
    int off = g_off[warp];

    float4 acc = make_float4(0.f, 0.f, 0.f, 0.f);
    const float4* y4 = reinterpret_cast<const float4*>(g_y);

    int e = off;
    // unroll by 2 for MLP
    for (; e + 2 <= off + cnt; e += 2) {
        uint2 e0 = g_edges[e];
        uint2 e1 = g_edges[e + 1];
        float v0 = __uint_as_float(e0.y);
        float v1 = __uint_as_float(e1.y);
        float4 y0 = y4[(size_t)e0.x * 32 + lane];
        float4 y1 = y4[(size_t)e1.x * 32 + lane];
        acc.x += v0 * y0.x + v1 * y1.x;
        acc.y += v0 * y0.y + v1 * y1.y;
        acc.z += v0 * y0.z + v1 * y1.z;
        acc.w += v0 * y0.w + v1 * y1.w;
    }
    if (e < off + cnt) {
        uint2 e0 = g_edges[e];
        float v0 = __uint_as_float(e0.y);
        float4 y0 = y4[(size_t)e0.x * 32 + lane];
        acc.x += v0 * y0.x; acc.y += v0 * y0.y;
        acc.z += v0 * y0.z; acc.w += v0 * y0.w;
    }

    float4* po = reinterpret_cast<float4*>(out) + (size_t)warp * 32 + lane;
    float4 o = *po;
    o.x += acc.x; o.y += acc.y; o.z += acc.z; o.w += acc.w;
    *po = o;
}

// ============================================================================
// Launch
// ============================================================================
extern "C" void kernel_launch(void* const* d_in, const int* in_sizes, int n_in,
                              void* d_out, int out_size) {
    const float* x     = (const float*)d_in[0];
    const int*   esrc  = (const int*)  d_in[1];
    const int*   edst  = (const int*)  d_in[2];
    const float* eval_ = (const float*)d_in[3];
    const float* W     = (const float*)d_in[4];
    const float* bias  = (const float*)d_in[5];
    float*       out   = (float*)d_out;

    const int N = in_sizes[0] / D;     // 100000
    const int E = in_sizes[1];         // 1600000

    // 1) split x -> bf16 hi/lo, zero histogram
    {
        int n4 = N * (D / 4);
        convert_kernel<<<(n4 + 255) / 256, 256>>>(x, n4, N);
    }
    // 2) CSR build: histogram -> scan -> permute
    hist_kernel<<<(E + 255) / 256, 256>>>(edst, E);
    scan_kernel<<<1, 1024>>>(N);
    fill_kernel<<<(E + 255) / 256, 256>>>(esrc, edst, eval_, E);
    // 3) persistent GEMM: d_out = x@W1 + b ; g_y = x@W2
    {
        static bool attr_set = false;
        if (!attr_set) {
            cudaFuncSetAttribute(gemm_kernel,
                                 cudaFuncAttributeMaxDynamicSharedMemorySize,
                                 SM_TOTAL);
            attr_set = true;
        }
        gemm_kernel<<<148, GT, SM_TOTAL>>>(W, bias, out, N);
    }
    // 4) CSR aggregate into d_out
    aggregate_kernel<<<(N * 32 + 255) / 256, 256>>>(out, N);
}